// round 9
// baseline (speedup 1.0000x reference)
#include <cuda_runtime.h>
#include <cuda_bf16.h>
#include <cstdint>
#include <math.h>

#define NN 50000
#define NE 800000
#define TT 12
#define NPB 128
#define NTILES ((NN + NPB - 1) / NPB)   // 391
#define PGRID 296                        // 2 CTAs x 148 SMs, persistent

// ---------------- device scratch (no allocations) ----------------
__device__ float g_deg[NN];
__device__ float g_agg[NN * 24];
__device__ int   g_is64;

// ---------------- preprocessing ----------------
__global__ void k_initprobe(const int* __restrict__ ei32) {
    int i = blockIdx.x * blockDim.x + threadIdx.x;
    int stride = gridDim.x * blockDim.x;
    for (int j = i; j < NN; j += stride) g_deg[j] = 0.0f;
    for (int j = i; j < NN * 24; j += stride) g_agg[j] = 0.0f;
    if (blockIdx.x == 0) {
        int nz = 0;
        for (int j = threadIdx.x; j < 1024; j += blockDim.x)
            if (ei32[2 * j + 1] != 0) nz = 1;
        int any = __syncthreads_or(nz);
        if (threadIdx.x == 0) g_is64 = any ? 0 : 1;
    }
}

__device__ __forceinline__ void load_edge(const int* ei32, int e, int& s, int& d) {
    if (g_is64) { s = ei32[2 * e]; d = ei32[2 * (NE + e)]; }
    else        { s = ei32[e];     d = ei32[NE + e]; }
}

__global__ void k_deg(const int* __restrict__ ei32) {
    int e = blockIdx.x * blockDim.x + threadIdx.x;
    if (e >= NE) return;
    int s, d;
    load_edge(ei32, e, s, d);
    atomicAdd(&g_deg[d], 1.0f);
}

__global__ void k_scatter(const int* __restrict__ ei32, const float* __restrict__ x) {
    int e = blockIdx.x * blockDim.x + threadIdx.x;
    if (e >= NE) return;
    int s, d;
    load_edge(ei32, e, s, d);
    float w = rsqrtf(g_deg[s] + 1.0f) * rsqrtf(g_deg[d] + 1.0f);
    const float4* xs = (const float4*)(x + (size_t)s * 24);
    float* ag = g_agg + (size_t)d * 24;
#pragma unroll
    for (int q = 0; q < 6; q++) {
        float4 v = xs[q];
        atomicAdd(&ag[4 * q + 0], w * v.x);
        atomicAdd(&ag[4 * q + 1], w * v.y);
        atomicAdd(&ag[4 * q + 2], w * v.z);
        atomicAdd(&ag[4 * q + 3], w * v.w);
    }
}

// ---------------- bf16 helpers ----------------
__device__ __forceinline__ float fhi(float x) {
    return __bfloat162float(__float2bfloat16_rn(x));
}
__device__ __forceinline__ uint32_t pk(float a, float b) {
    __nv_bfloat162 t = __floats2bfloat162_rn(a, b);
    return *reinterpret_cast<uint32_t*>(&t);
}
__device__ __forceinline__ float2 upk(uint32_t u) {
    __nv_bfloat162 t = *reinterpret_cast<__nv_bfloat162*>(&u);
    return make_float2(__low2float(t), __high2float(t));
}

// m16n8k16 row.col bf16 MMA, fp32 accumulate
__device__ __forceinline__ void mma16816(float* d, const uint32_t* a,
                                         uint32_t b0, uint32_t b1) {
    asm volatile(
        "mma.sync.aligned.m16n8k16.row.col.f32.bf16.bf16.f32 "
        "{%0,%1,%2,%3}, {%4,%5,%6,%7}, {%8,%9}, {%0,%1,%2,%3};"
        : "+f"(d[0]), "+f"(d[1]), "+f"(d[2]), "+f"(d[3])
        : "r"(a[0]), "r"(a[1]), "r"(a[2]), "r"(a[3]), "r"(b0), "r"(b1));
}

// ---------------- smem layout (bytes) ----------------
#define SM_B1    0          // 128 frags x 32 lanes x 16B = 64KB (rz: K=128,N=128)
#define SM_B2    65536      // 16KB (Wih_n: K=64,N=64)
#define SM_B3    81920      // 16KB (Whh_n)
#define SM_XA    98304      // float2[12][128] = 12KB
#define SM_WG3   110592     // float4[64] : {wg0, wg1, bg, 0}
#define SM_BIAS  111616     // float4[64] : {br, bz, bin, bhn}
#define SM_WFC   112640     // float[64]
#define SM_TOTAL 112896     // 2 CTAs per SM

__global__ void __launch_bounds__(256, 2)
k_fused(const float* __restrict__ x,
        const float* __restrict__ W_gcn, const float* __restrict__ b_gcn,
        const float* __restrict__ W_ih,  const float* __restrict__ W_hh,
        const float* __restrict__ b_ih,  const float* __restrict__ b_hh,
        const float* __restrict__ W_fc,  const float* __restrict__ b_fc,
        float* __restrict__ out) {
    extern __shared__ char smem[];
    const int tid  = threadIdx.x;
    const int wid  = tid >> 5;
    const int lane = tid & 31;
    const int gid  = lane >> 2;
    const int tig  = lane & 3;
    const int n0 = wid * 16 + gid;
    const int n1 = n0 + 8;

    // ---- build B fragments ONCE per persistent CTA ----
    for (int i = tid; i < 6144; i += 256) {
        int f, l;
        const float* Wrow;
        int k0;
        uint32_t dst;
        if (i < 4096) {                       // B1: rz, 8kt x 16nt
            f = i >> 5; l = i & 31;
            int kt = f >> 4, nt = f & 15;
            int g = l >> 2, tg = l & 3;
            int j = 8 * nt + g;
            k0 = 16 * kt + 2 * tg;
            Wrow = (kt < 4) ? (W_ih + j * 64 + k0) : (W_hh + j * 64 + (k0 - 64));
            dst = SM_B1 + (uint32_t)(f * 32 + l) * 16;
        } else if (i < 5120) {                // B2: Wih_n
            int ii = i - 4096;
            f = ii >> 5; l = ii & 31;
            int kt = f >> 3, nt = f & 7;
            int g = l >> 2, tg = l & 3;
            int j = 8 * nt + g;
            k0 = 16 * kt + 2 * tg;
            Wrow = W_ih + (128 + j) * 64 + k0;
            dst = SM_B2 + (uint32_t)(f * 32 + l) * 16;
        } else {                              // B3: Whh_n
            int ii = i - 5120;
            f = ii >> 5; l = ii & 31;
            int kt = f >> 3, nt = f & 7;
            int g = l >> 2, tg = l & 3;
            int j = 8 * nt + g;
            k0 = 16 * kt + 2 * tg;
            Wrow = W_hh + (128 + j) * 64 + k0;
            dst = SM_B3 + (uint32_t)(f * 32 + l) * 16;
        }
        float w0 = Wrow[0], w1 = Wrow[1], w8 = Wrow[8], w9 = Wrow[9];
        float h0 = fhi(w0), h1 = fhi(w1), h8 = fhi(w8), h9 = fhi(w9);
        uint4 v;
        v.x = pk(h0, h1);
        v.y = pk(h8, h9);
        v.z = pk(w0 - h0, w1 - h1);
        v.w = pk(w8 - h8, w9 - h9);
        *(uint4*)(smem + dst) = v;
    }
    if (tid < 64) {
        float4* wg3 = (float4*)(smem + SM_WG3);
        wg3[tid] = make_float4(W_gcn[tid], W_gcn[64 + tid], b_gcn[tid], 0.0f);
        float4* bia = (float4*)(smem + SM_BIAS);
        bia[tid] = make_float4(b_ih[tid] + b_hh[tid],
                               b_ih[64 + tid] + b_hh[64 + tid],
                               b_ih[128 + tid], b_hh[128 + tid]);
        ((float*)(smem + SM_WFC))[tid] = W_fc[tid];
    }

    const float4* sWG3  = (const float4*)(smem + SM_WG3);
    const float4* sBIAS = (const float4*)(smem + SM_BIAS);
    const float*  sWFC  = (const float*)(smem + SM_WFC);
    float* sXA = (float*)(smem + SM_XA);
    const float bfc = b_fc[0];

    // ---- persistent tile loop ----
    for (int tile = blockIdx.x; tile < NTILES; tile += PGRID) {
        const int node0 = tile * NPB;
        __syncthreads();   // previous tile's XA reads complete

        for (int i = tid; i < NPB * 24; i += 256) {
            int n = i / 24, cc = i - n * 24;
            int t = cc >> 1, c = cc & 1;
            int node = node0 + n;
            float v = 0.0f;
            if (node < NN) {
                float dv = rsqrtf(g_deg[node] + 1.0f);
                v = g_agg[(size_t)node * 24 + cc] + dv * dv * x[(size_t)node * 24 + cc];
            }
            sXA[(t * 128 + n) * 2 + c] = v;
        }
        __syncthreads();

        // hidden state packed as bf16 hi/lo A-fragments
        uint32_t hh[4][4], hl[4][4];
#pragma unroll
        for (int kt = 0; kt < 4; kt++)
#pragma unroll
            for (int q = 0; q < 4; q++) { hh[kt][q] = 0u; hl[kt][q] = 0u; }

#pragma unroll 1
        for (int t = 0; t < TT; t++) {
            float2 xaA = *(const float2*)(sXA + (t * 128 + n0) * 2);
            float2 xaB = *(const float2*)(sXA + (t * 128 + n1) * 2);

            // S fragments (hi/lo)
            uint32_t sfH[4][4], sfL[4][4];
#pragma unroll
            for (int kt = 0; kt < 4; kt++) {
                int k0 = 16 * kt + 2 * tig;
                float4 g0 = sWG3[k0], g1 = sWG3[k0 + 1];
                float4 g8 = sWG3[k0 + 8], g9 = sWG3[k0 + 9];
                float s00 = fmaxf(fmaf(xaA.x, g0.x, fmaf(xaA.y, g0.y, g0.z)), 0.0f);
                float s01 = fmaxf(fmaf(xaA.x, g1.x, fmaf(xaA.y, g1.y, g1.z)), 0.0f);
                float s10 = fmaxf(fmaf(xaB.x, g0.x, fmaf(xaB.y, g0.y, g0.z)), 0.0f);
                float s11 = fmaxf(fmaf(xaB.x, g1.x, fmaf(xaB.y, g1.y, g1.z)), 0.0f);
                float s08 = fmaxf(fmaf(xaA.x, g8.x, fmaf(xaA.y, g8.y, g8.z)), 0.0f);
                float s09 = fmaxf(fmaf(xaA.x, g9.x, fmaf(xaA.y, g9.y, g9.z)), 0.0f);
                float s18 = fmaxf(fmaf(xaB.x, g8.x, fmaf(xaB.y, g8.y, g8.z)), 0.0f);
                float s19 = fmaxf(fmaf(xaB.x, g9.x, fmaf(xaB.y, g9.y, g9.z)), 0.0f);
                float h00 = fhi(s00), h01 = fhi(s01), h10 = fhi(s10), h11 = fhi(s11);
                float h08 = fhi(s08), h09 = fhi(s09), h18 = fhi(s18), h19 = fhi(s19);
                sfH[kt][0] = pk(h00, h01); sfH[kt][1] = pk(h10, h11);
                sfH[kt][2] = pk(h08, h09); sfH[kt][3] = pk(h18, h19);
                sfL[kt][0] = pk(s00 - h00, s01 - h01);
                sfL[kt][1] = pk(s10 - h10, s11 - h11);
                sfL[kt][2] = pk(s08 - h08, s09 - h09);
                sfL[kt][3] = pk(s18 - h18, s19 - h19);
            }

            uint32_t nhh[4][4], nhl[4][4];
#pragma unroll
            for (int nt = 0; nt < 8; nt++) {
                // split accumulators: S-part and H-part chains are independent
                float aRs[4] = {0, 0, 0, 0}, aRh[4] = {0, 0, 0, 0};
                float aZs[4] = {0, 0, 0, 0}, aZh[4] = {0, 0, 0, 0};
                float aI[4]  = {0, 0, 0, 0}, aN[4]  = {0, 0, 0, 0};
#pragma unroll
                for (int kt = 0; kt < 4; kt++) {
                    // S-part of R,Z
                    uint4 bR = *(const uint4*)(smem + SM_B1 +
                                 (uint32_t)((kt * 16 + nt) * 32 + lane) * 16);
                    mma16816(aRs, sfH[kt], bR.x, bR.y);
                    mma16816(aRs, sfH[kt], bR.z, bR.w);
                    mma16816(aRs, sfL[kt], bR.x, bR.y);
                    uint4 bZ = *(const uint4*)(smem + SM_B1 +
                                 (uint32_t)((kt * 16 + nt + 8) * 32 + lane) * 16);
                    mma16816(aZs, sfH[kt], bZ.x, bZ.y);
                    mma16816(aZs, sfH[kt], bZ.z, bZ.w);
                    mma16816(aZs, sfL[kt], bZ.x, bZ.y);
                    // H-part of R,Z
                    uint4 cR = *(const uint4*)(smem + SM_B1 +
                                 (uint32_t)(((kt + 4) * 16 + nt) * 32 + lane) * 16);
                    mma16816(aRh, hh[kt], cR.x, cR.y);
                    mma16816(aRh, hh[kt], cR.z, cR.w);
                    mma16816(aRh, hl[kt], cR.x, cR.y);
                    uint4 cZ = *(const uint4*)(smem + SM_B1 +
                                 (uint32_t)(((kt + 4) * 16 + nt + 8) * 32 + lane) * 16);
                    mma16816(aZh, hh[kt], cZ.x, cZ.y);
                    mma16816(aZh, hh[kt], cZ.z, cZ.w);
                    mma16816(aZh, hl[kt], cZ.x, cZ.y);
                    // i_n (S only) and h_n (H only)
                    uint4 b2 = *(const uint4*)(smem + SM_B2 +
                                 (uint32_t)((kt * 8 + nt) * 32 + lane) * 16);
                    mma16816(aI, sfH[kt], b2.x, b2.y);
                    mma16816(aI, sfH[kt], b2.z, b2.w);
                    mma16816(aI, sfL[kt], b2.x, b2.y);
                    uint4 b3 = *(const uint4*)(smem + SM_B3 +
                                 (uint32_t)((kt * 8 + nt) * 32 + lane) * 16);
                    mma16816(aN, hh[kt], b3.x, b3.y);
                    mma16816(aN, hh[kt], b3.z, b3.w);
                    mma16816(aN, hl[kt], b3.x, b3.y);
                }
                int kt2 = nt >> 1, base = (nt & 1) * 2;
                float2 oh0H = upk(hh[kt2][base]),     oh0L = upk(hl[kt2][base]);
                float2 oh1H = upk(hh[kt2][base + 1]), oh1L = upk(hl[kt2][base + 1]);
                float hold[4] = { oh0H.x + oh0L.x, oh0H.y + oh0L.y,
                                  oh1H.x + oh1L.x, oh1H.y + oh1L.y };
                int j0 = 8 * nt + 2 * tig;
                float4 bj0 = sBIAS[j0];
                float4 bj1 = sBIAS[j0 + 1];
                float hn[4];
#pragma unroll
                for (int q = 0; q < 4; q++) {
                    float4 bb = (q & 1) ? bj1 : bj0;
                    float r  = 1.0f / (1.0f + __expf(-(aRs[q] + aRh[q] + bb.x)));
                    float z  = 1.0f / (1.0f + __expf(-(aZs[q] + aZh[q] + bb.y)));
                    float nn = tanhf(fmaf(r, aN[q] + bb.w, aI[q] + bb.z));
                    hn[q] = fmaf(z, hold[q] - nn, nn);
                }
                float p0 = fhi(hn[0]), p1 = fhi(hn[1]);
                float p2 = fhi(hn[2]), p3 = fhi(hn[3]);
                nhh[kt2][base]     = pk(p0, p1);
                nhh[kt2][base + 1] = pk(p2, p3);
                nhl[kt2][base]     = pk(hn[0] - p0, hn[1] - p1);
                nhl[kt2][base + 1] = pk(hn[2] - p2, hn[3] - p3);
            }
#pragma unroll
            for (int kt = 0; kt < 4; kt++)
#pragma unroll
                for (int q = 0; q < 4; q++) { hh[kt][q] = nhh[kt][q]; hl[kt][q] = nhl[kt][q]; }
        }

        // FC readout
        float pA = 0.0f, pB = 0.0f;
#pragma unroll
        for (int nt = 0; nt < 8; nt++) {
            int kt2 = nt >> 1, base = (nt & 1) * 2;
            float2 aHv = upk(hh[kt2][base]),     aLv = upk(hl[kt2][base]);
            float2 bHv = upk(hh[kt2][base + 1]), bLv = upk(hl[kt2][base + 1]);
            int j0 = 8 * nt + 2 * tig;
            float w0 = sWFC[j0], w1 = sWFC[j0 + 1];
            pA = fmaf(aHv.x + aLv.x, w0, fmaf(aHv.y + aLv.y, w1, pA));
            pB = fmaf(bHv.x + bLv.x, w0, fmaf(bHv.y + bLv.y, w1, pB));
        }
        pA += __shfl_xor_sync(0xFFFFFFFF, pA, 1);
        pA += __shfl_xor_sync(0xFFFFFFFF, pA, 2);
        pB += __shfl_xor_sync(0xFFFFFFFF, pB, 1);
        pB += __shfl_xor_sync(0xFFFFFFFF, pB, 2);
        if (tig == 0) {
            int nodeA = node0 + n0;
            int nodeB = node0 + n1;
            if (nodeA < NN) out[nodeA] = pA + bfc;
            if (nodeB < NN) out[nodeB] = pB + bfc;
        }
    }
}

// ---------------- launch ----------------
extern "C" void kernel_launch(void* const* d_in, const int* in_sizes, int n_in,
                              void* d_out, int out_size) {
    const float* x     = (const float*)d_in[0];
    const int*   ei32  = (const int*)d_in[1];
    const float* W_gcn = (const float*)d_in[2];
    const float* b_gcn = (const float*)d_in[3];
    const float* W_ih  = (const float*)d_in[4];
    const float* W_hh  = (const float*)d_in[5];
    const float* b_ih  = (const float*)d_in[6];
    const float* b_hh  = (const float*)d_in[7];
    const float* W_fc  = (const float*)d_in[8];
    const float* b_fc  = (const float*)d_in[9];
    float* out = (float*)d_out;

    static bool attr_set = false;
    if (!attr_set) {
        cudaFuncSetAttribute(k_fused, cudaFuncAttributeMaxDynamicSharedMemorySize,
                             SM_TOTAL);
        attr_set = true;
    }

    k_initprobe<<<256, 256>>>(ei32);
    k_deg<<<(NE + 255) / 256, 256>>>(ei32);
    k_scatter<<<(NE + 255) / 256, 256>>>(ei32, x);
    k_fused<<<PGRID, 256, SM_TOTAL>>>(
        x, W_gcn, b_gcn, W_ih, W_hh, b_ih, b_hh, W_fc, b_fc, out);
}

// round 10
// speedup vs baseline: 1.2657x; 1.2657x over previous
#include <cuda_runtime.h>
#include <cuda_bf16.h>
#include <cstdint>
#include <math.h>

#define NN 50000
#define NE 800000
#define TT 12
#define NPB 128

// ---------------- device scratch (no allocations) ----------------
__device__ float g_deg[NN];
__device__ float g_agg[NN * 24];
__device__ int   g_is64;

// ---------------- preprocessing ----------------
__global__ void k_initprobe(const int* __restrict__ ei32) {
    int i = blockIdx.x * blockDim.x + threadIdx.x;
    int stride = gridDim.x * blockDim.x;
    for (int j = i; j < NN; j += stride) g_deg[j] = 0.0f;
    for (int j = i; j < NN * 24; j += stride) g_agg[j] = 0.0f;
    if (blockIdx.x == 0) {
        int nz = 0;
        for (int j = threadIdx.x; j < 1024; j += blockDim.x)
            if (ei32[2 * j + 1] != 0) nz = 1;
        int any = __syncthreads_or(nz);
        if (threadIdx.x == 0) g_is64 = any ? 0 : 1;
    }
}

__device__ __forceinline__ void load_edge(const int* ei32, int e, int& s, int& d) {
    if (g_is64) { s = ei32[2 * e]; d = ei32[2 * (NE + e)]; }
    else        { s = ei32[e];     d = ei32[NE + e]; }
}

__global__ void k_deg(const int* __restrict__ ei32) {
    int e = blockIdx.x * blockDim.x + threadIdx.x;
    if (e >= NE) return;
    int s, d;
    load_edge(ei32, e, s, d);
    atomicAdd(&g_deg[d], 1.0f);
}

__global__ void k_scatter(const int* __restrict__ ei32, const float* __restrict__ x) {
    int e = blockIdx.x * blockDim.x + threadIdx.x;
    if (e >= NE) return;
    int s, d;
    load_edge(ei32, e, s, d);
    float w = rsqrtf(g_deg[s] + 1.0f) * rsqrtf(g_deg[d] + 1.0f);
    const float4* xs = (const float4*)(x + (size_t)s * 24);
    float* ag = g_agg + (size_t)d * 24;
#pragma unroll
    for (int q = 0; q < 6; q++) {
        float4 v = xs[q];
        atomicAdd(&ag[4 * q + 0], w * v.x);
        atomicAdd(&ag[4 * q + 1], w * v.y);
        atomicAdd(&ag[4 * q + 2], w * v.z);
        atomicAdd(&ag[4 * q + 3], w * v.w);
    }
}

// ---------------- fast math (MUFU-based) ----------------
__device__ __forceinline__ float fsigmoid(float x) {
    float e, r;
    asm("ex2.approx.ftz.f32 %0, %1;" : "=f"(e) : "f"(-x * 1.4426950408889634f));
    asm("rcp.approx.ftz.f32 %0, %1;" : "=f"(r) : "f"(1.0f + e));
    return r;
}
__device__ __forceinline__ float ftanh(float x) {
    float r;
    asm("tanh.approx.f32 %0, %1;" : "=f"(r) : "f"(x));
    return r;
}

// ---------------- bf16 helpers ----------------
__device__ __forceinline__ float fhi(float x) {
    return __bfloat162float(__float2bfloat16_rn(x));
}
__device__ __forceinline__ uint32_t pk(float a, float b) {
    __nv_bfloat162 t = __floats2bfloat162_rn(a, b);
    return *reinterpret_cast<uint32_t*>(&t);
}
__device__ __forceinline__ float2 upk(uint32_t u) {
    __nv_bfloat162 t = *reinterpret_cast<__nv_bfloat162*>(&u);
    return make_float2(__low2float(t), __high2float(t));
}

// m16n8k16 row.col bf16 MMA, fp32 accumulate
__device__ __forceinline__ void mma16816(float* d, const uint32_t* a,
                                         uint32_t b0, uint32_t b1) {
    asm volatile(
        "mma.sync.aligned.m16n8k16.row.col.f32.bf16.bf16.f32 "
        "{%0,%1,%2,%3}, {%4,%5,%6,%7}, {%8,%9}, {%0,%1,%2,%3};"
        : "+f"(d[0]), "+f"(d[1]), "+f"(d[2]), "+f"(d[3])
        : "r"(a[0]), "r"(a[1]), "r"(a[2]), "r"(a[3]), "r"(b0), "r"(b1));
}

// ---------------- smem layout (bytes) ----------------
#define SM_B1    0          // 128 frags x 32 lanes x 16B = 64KB (rz: K=128,N=128)
#define SM_B2    65536      // 16KB (Wih_n: K=64,N=64)
#define SM_B3    81920      // 16KB (Whh_n)
#define SM_XA    98304      // float2[12][128] = 12KB
#define SM_WG3   110592     // float4[64] : {wg0, wg1, bg, 0}
#define SM_BIAS  111616     // float4[64] : {br, bz, bin, bhn}
#define SM_WFC   112640     // float[64]
#define SM_TOTAL 112896     // 2 CTAs per SM

__global__ void __launch_bounds__(256, 2)
k_fused(const float* __restrict__ x,
        const float* __restrict__ W_gcn, const float* __restrict__ b_gcn,
        const float* __restrict__ W_ih,  const float* __restrict__ W_hh,
        const float* __restrict__ b_ih,  const float* __restrict__ b_hh,
        const float* __restrict__ W_fc,  const float* __restrict__ b_fc,
        float* __restrict__ out) {
    extern __shared__ char smem[];
    const int tid  = threadIdx.x;
    const int wid  = tid >> 5;
    const int lane = tid & 31;
    const int gid  = lane >> 2;
    const int tig  = lane & 3;
    const int node0 = blockIdx.x * NPB;
    const int n0 = wid * 16 + gid;
    const int n1 = n0 + 8;

    // ---- build B fragments (hi/lo interleaved, fragment-major) ----
    for (int i = tid; i < 6144; i += 256) {
        int f, l;
        const float* Wrow;
        int k0;
        uint32_t dst;
        if (i < 4096) {                       // B1: rz, 8kt x 16nt
            f = i >> 5; l = i & 31;
            int kt = f >> 4, nt = f & 15;
            int g = l >> 2, tg = l & 3;
            int j = 8 * nt + g;
            k0 = 16 * kt + 2 * tg;
            Wrow = (kt < 4) ? (W_ih + j * 64 + k0) : (W_hh + j * 64 + (k0 - 64));
            dst = SM_B1 + (uint32_t)(f * 32 + l) * 16;
        } else if (i < 5120) {                // B2: Wih_n
            int ii = i - 4096;
            f = ii >> 5; l = ii & 31;
            int kt = f >> 3, nt = f & 7;
            int g = l >> 2, tg = l & 3;
            int j = 8 * nt + g;
            k0 = 16 * kt + 2 * tg;
            Wrow = W_ih + (128 + j) * 64 + k0;
            dst = SM_B2 + (uint32_t)(f * 32 + l) * 16;
        } else {                              // B3: Whh_n
            int ii = i - 5120;
            f = ii >> 5; l = ii & 31;
            int kt = f >> 3, nt = f & 7;
            int g = l >> 2, tg = l & 3;
            int j = 8 * nt + g;
            k0 = 16 * kt + 2 * tg;
            Wrow = W_hh + (128 + j) * 64 + k0;
            dst = SM_B3 + (uint32_t)(f * 32 + l) * 16;
        }
        float w0 = Wrow[0], w1 = Wrow[1], w8 = Wrow[8], w9 = Wrow[9];
        float h0 = fhi(w0), h1 = fhi(w1), h8 = fhi(w8), h9 = fhi(w9);
        uint4 v;
        v.x = pk(h0, h1);
        v.y = pk(h8, h9);
        v.z = pk(w0 - h0, w1 - h1);
        v.w = pk(w8 - h8, w9 - h9);
        *(uint4*)(smem + dst) = v;
    }

    // ---- XA: agg + selfnorm*x, layout float2[t][n] ----
    float* sXA = (float*)(smem + SM_XA);
    for (int i = tid; i < NPB * 24; i += 256) {
        int n = i / 24, cc = i - n * 24;
        int t = cc >> 1, c = cc & 1;
        int node = node0 + n;
        float v = 0.0f;
        if (node < NN) {
            float dv = rsqrtf(g_deg[node] + 1.0f);
            v = g_agg[(size_t)node * 24 + cc] + dv * dv * x[(size_t)node * 24 + cc];
        }
        sXA[(t * 128 + n) * 2 + c] = v;
    }
    if (tid < 64) {
        float4* wg3 = (float4*)(smem + SM_WG3);
        wg3[tid] = make_float4(W_gcn[tid], W_gcn[64 + tid], b_gcn[tid], 0.0f);
        float4* bia = (float4*)(smem + SM_BIAS);
        bia[tid] = make_float4(b_ih[tid] + b_hh[tid],
                               b_ih[64 + tid] + b_hh[64 + tid],
                               b_ih[128 + tid], b_hh[128 + tid]);
        ((float*)(smem + SM_WFC))[tid] = W_fc[tid];
    }
    __syncthreads();

    const float4* sWG3  = (const float4*)(smem + SM_WG3);
    const float4* sBIAS = (const float4*)(smem + SM_BIAS);
    const float*  sWFC  = (const float*)(smem + SM_WFC);

    // ---- hidden state kept PACKED as bf16 hi/lo A-fragments ----
    uint32_t hh[4][4], hl[4][4];
#pragma unroll
    for (int kt = 0; kt < 4; kt++)
#pragma unroll
        for (int q = 0; q < 4; q++) { hh[kt][q] = 0u; hl[kt][q] = 0u; }

#pragma unroll 1
    for (int t = 0; t < TT; t++) {
        float2 xaA = *(const float2*)(sXA + (t * 128 + n0) * 2);
        float2 xaB = *(const float2*)(sXA + (t * 128 + n1) * 2);

        // ---- S fragments (hi/lo) ----
        uint32_t sfH[4][4], sfL[4][4];
#pragma unroll
        for (int kt = 0; kt < 4; kt++) {
            int k0 = 16 * kt + 2 * tig;
            float4 g0 = sWG3[k0], g1 = sWG3[k0 + 1];
            float4 g8 = sWG3[k0 + 8], g9 = sWG3[k0 + 9];
            float s00 = fmaxf(fmaf(xaA.x, g0.x, fmaf(xaA.y, g0.y, g0.z)), 0.0f);
            float s01 = fmaxf(fmaf(xaA.x, g1.x, fmaf(xaA.y, g1.y, g1.z)), 0.0f);
            float s10 = fmaxf(fmaf(xaB.x, g0.x, fmaf(xaB.y, g0.y, g0.z)), 0.0f);
            float s11 = fmaxf(fmaf(xaB.x, g1.x, fmaf(xaB.y, g1.y, g1.z)), 0.0f);
            float s08 = fmaxf(fmaf(xaA.x, g8.x, fmaf(xaA.y, g8.y, g8.z)), 0.0f);
            float s09 = fmaxf(fmaf(xaA.x, g9.x, fmaf(xaA.y, g9.y, g9.z)), 0.0f);
            float s18 = fmaxf(fmaf(xaB.x, g8.x, fmaf(xaB.y, g8.y, g8.z)), 0.0f);
            float s19 = fmaxf(fmaf(xaB.x, g9.x, fmaf(xaB.y, g9.y, g9.z)), 0.0f);
            float h00 = fhi(s00), h01 = fhi(s01), h10 = fhi(s10), h11 = fhi(s11);
            float h08 = fhi(s08), h09 = fhi(s09), h18 = fhi(s18), h19 = fhi(s19);
            sfH[kt][0] = pk(h00, h01); sfH[kt][1] = pk(h10, h11);
            sfH[kt][2] = pk(h08, h09); sfH[kt][3] = pk(h18, h19);
            sfL[kt][0] = pk(s00 - h00, s01 - h01);
            sfL[kt][1] = pk(s10 - h10, s11 - h11);
            sfL[kt][2] = pk(s08 - h08, s09 - h09);
            sfL[kt][3] = pk(s18 - h18, s19 - h19);
        }

        // ---- per-nt: accumulate gate tiles, update h, repack ----
        uint32_t nhh[4][4], nhl[4][4];
#pragma unroll
        for (int nt = 0; nt < 8; nt++) {
            float aR[4] = {0, 0, 0, 0}, aZ[4] = {0, 0, 0, 0};
            float aI[4] = {0, 0, 0, 0}, aN[4] = {0, 0, 0, 0};
#pragma unroll
            for (int kt = 0; kt < 8; kt++) {
                const uint32_t* xH = (kt < 4) ? sfH[kt] : hh[kt - 4];
                const uint32_t* xL = (kt < 4) ? sfL[kt] : hl[kt - 4];
                uint4 bR = *(const uint4*)(smem + SM_B1 +
                             (uint32_t)((kt * 16 + nt) * 32 + lane) * 16);
                mma16816(aR, xH, bR.x, bR.y);
                mma16816(aR, xH, bR.z, bR.w);
                mma16816(aR, xL, bR.x, bR.y);
                uint4 bZ = *(const uint4*)(smem + SM_B1 +
                             (uint32_t)((kt * 16 + nt + 8) * 32 + lane) * 16);
                mma16816(aZ, xH, bZ.x, bZ.y);
                mma16816(aZ, xH, bZ.z, bZ.w);
                mma16816(aZ, xL, bZ.x, bZ.y);
                if (kt < 4) {
                    uint4 b2 = *(const uint4*)(smem + SM_B2 +
                                 (uint32_t)((kt * 8 + nt) * 32 + lane) * 16);
                    mma16816(aI, sfH[kt], b2.x, b2.y);
                    mma16816(aI, sfH[kt], b2.z, b2.w);
                    mma16816(aI, sfL[kt], b2.x, b2.y);
                    uint4 b3 = *(const uint4*)(smem + SM_B3 +
                                 (uint32_t)((kt * 8 + nt) * 32 + lane) * 16);
                    mma16816(aN, hh[kt], b3.x, b3.y);
                    mma16816(aN, hh[kt], b3.z, b3.w);
                    mma16816(aN, hl[kt], b3.x, b3.y);
                }
            }
            int kt2 = nt >> 1, base = (nt & 1) * 2;
            float2 oh0H = upk(hh[kt2][base]),     oh0L = upk(hl[kt2][base]);
            float2 oh1H = upk(hh[kt2][base + 1]), oh1L = upk(hl[kt2][base + 1]);
            float hold[4] = { oh0H.x + oh0L.x, oh0H.y + oh0L.y,
                              oh1H.x + oh1L.x, oh1H.y + oh1L.y };
            int j0 = 8 * nt + 2 * tig;
            float4 bj0 = sBIAS[j0];
            float4 bj1 = sBIAS[j0 + 1];
            float hn[4];
#pragma unroll
            for (int q = 0; q < 4; q++) {
                float4 bb = (q & 1) ? bj1 : bj0;
                float r  = fsigmoid(aR[q] + bb.x);
                float z  = fsigmoid(aZ[q] + bb.y);
                float nn = ftanh(fmaf(r, aN[q] + bb.w, aI[q] + bb.z));
                hn[q] = fmaf(z, hold[q] - nn, nn);
            }
            float p0 = fhi(hn[0]), p1 = fhi(hn[1]);
            float p2 = fhi(hn[2]), p3 = fhi(hn[3]);
            nhh[kt2][base]     = pk(p0, p1);
            nhh[kt2][base + 1] = pk(p2, p3);
            nhl[kt2][base]     = pk(hn[0] - p0, hn[1] - p1);
            nhl[kt2][base + 1] = pk(hn[2] - p2, hn[3] - p3);
        }
#pragma unroll
        for (int kt = 0; kt < 4; kt++)
#pragma unroll
            for (int q = 0; q < 4; q++) { hh[kt][q] = nhh[kt][q]; hl[kt][q] = nhl[kt][q]; }
    }

    // ---- FC readout ----
    const float*  sWFC2 = sWFC;
    float pA = 0.0f, pB = 0.0f;
#pragma unroll
    for (int nt = 0; nt < 8; nt++) {
        int kt2 = nt >> 1, base = (nt & 1) * 2;
        float2 aHv = upk(hh[kt2][base]),     aLv = upk(hl[kt2][base]);
        float2 bHv = upk(hh[kt2][base + 1]), bLv = upk(hl[kt2][base + 1]);
        int j0 = 8 * nt + 2 * tig;
        float w0 = sWFC2[j0], w1 = sWFC2[j0 + 1];
        pA = fmaf(aHv.x + aLv.x, w0, fmaf(aHv.y + aLv.y, w1, pA));
        pB = fmaf(bHv.x + bLv.x, w0, fmaf(bHv.y + bLv.y, w1, pB));
    }
    pA += __shfl_xor_sync(0xFFFFFFFF, pA, 1);
    pA += __shfl_xor_sync(0xFFFFFFFF, pA, 2);
    pB += __shfl_xor_sync(0xFFFFFFFF, pB, 1);
    pB += __shfl_xor_sync(0xFFFFFFFF, pB, 2);
    if (tig == 0) {
        float bfc = b_fc[0];
        int nodeA = node0 + n0;
        int nodeB = node0 + n1;
        if (nodeA < NN) out[nodeA] = pA + bfc;
        if (nodeB < NN) out[nodeB] = pB + bfc;
    }
}

// ---------------- launch ----------------
extern "C" void kernel_launch(void* const* d_in, const int* in_sizes, int n_in,
                              void* d_out, int out_size) {
    const float* x     = (const float*)d_in[0];
    const int*   ei32  = (const int*)d_in[1];
    const float* W_gcn = (const float*)d_in[2];
    const float* b_gcn = (const float*)d_in[3];
    const float* W_ih  = (const float*)d_in[4];
    const float* W_hh  = (const float*)d_in[5];
    const float* b_ih  = (const float*)d_in[6];
    const float* b_hh  = (const float*)d_in[7];
    const float* W_fc  = (const float*)d_in[8];
    const float* b_fc  = (const float*)d_in[9];
    float* out = (float*)d_out;

    static bool attr_set = false;
    if (!attr_set) {
        cudaFuncSetAttribute(k_fused, cudaFuncAttributeMaxDynamicSharedMemorySize,
                             SM_TOTAL);
        attr_set = true;
    }

    k_initprobe<<<256, 256>>>(ei32);
    k_deg<<<(NE + 255) / 256, 256>>>(ei32);
    k_scatter<<<(NE + 255) / 256, 256>>>(ei32, x);
    k_fused<<<(NN + NPB - 1) / NPB, 256, SM_TOTAL>>>(
        x, W_gcn, b_gcn, W_ih, W_hh, b_ih, b_hh, W_fc, b_fc, out);
}

// round 11
// speedup vs baseline: 1.5594x; 1.2320x over previous
#include <cuda_runtime.h>
#include <cuda_bf16.h>
#include <cstdint>
#include <math.h>

#define NN 50000
#define NE 800000
#define TT 12
#define NPB 128
#define SCAN_BLOCKS 196   // ceil(50000/256)

// ---------------- device scratch (no allocations) ----------------
__device__ int   g_cnt[NN];
__device__ int   g_off[NN];
__device__ int   g_fill[NN];
__device__ int   g_srcs[NE];
__device__ float g_dinv[NN];
__device__ float g_agg[NN * 24];    // raw: sum_e dinv[src]*x[src][c]
__device__ int   g_bsum[256];
__device__ int   g_bpre[256];
__device__ int   g_is64;

// ---------------- preprocessing: CSR build + gather ----------------
__global__ void k_initprobe(const int* __restrict__ ei32) {
    int i = blockIdx.x * blockDim.x + threadIdx.x;
    int stride = gridDim.x * blockDim.x;
    for (int j = i; j < NN; j += stride) g_cnt[j] = 0;
    if (blockIdx.x == 0) {
        int nz = 0;
        for (int j = threadIdx.x; j < 1024; j += blockDim.x)
            if (ei32[2 * j + 1] != 0) nz = 1;
        int any = __syncthreads_or(nz);
        if (threadIdx.x == 0) g_is64 = any ? 0 : 1;
    }
}

__device__ __forceinline__ void load_edge(const int* ei32, int e, int& s, int& d) {
    if (g_is64) { s = ei32[2 * e]; d = ei32[2 * (NE + e)]; }
    else        { s = ei32[e];     d = ei32[NE + e]; }
}

__global__ void k_count(const int* __restrict__ ei32) {
    int e = blockIdx.x * blockDim.x + threadIdx.x;
    if (e >= NE) return;
    int s, d;
    load_edge(ei32, e, s, d);
    atomicAdd(&g_cnt[d], 1);
}

// block-local inclusive scan -> exclusive offsets + block sums
__global__ void k_scan1() {
    __shared__ int sc[256];
    int tid = threadIdx.x;
    int i = blockIdx.x * 256 + tid;
    int v = (i < NN) ? g_cnt[i] : 0;
    sc[tid] = v;
    __syncthreads();
#pragma unroll
    for (int ofs = 1; ofs < 256; ofs <<= 1) {
        int t = (tid >= ofs) ? sc[tid - ofs] : 0;
        __syncthreads();
        sc[tid] += t;
        __syncthreads();
    }
    if (i < NN) g_off[i] = sc[tid] - v;       // exclusive within block
    if (tid == 255) g_bsum[blockIdx.x] = sc[255];
}

__global__ void k_scan2() {
    __shared__ int sc[256];
    int tid = threadIdx.x;
    int v = (tid < SCAN_BLOCKS) ? g_bsum[tid] : 0;
    sc[tid] = v;
    __syncthreads();
#pragma unroll
    for (int ofs = 1; ofs < 256; ofs <<= 1) {
        int t = (tid >= ofs) ? sc[tid - ofs] : 0;
        __syncthreads();
        sc[tid] += t;
        __syncthreads();
    }
    g_bpre[tid] = sc[tid] - v;                // exclusive block prefix
}

__global__ void k_scan3() {
    int i = blockIdx.x * 256 + threadIdx.x;
    if (i >= NN) return;
    int off = g_off[i] + g_bpre[blockIdx.x];
    g_off[i]  = off;
    g_fill[i] = off;
    g_dinv[i] = rsqrtf((float)g_cnt[i] + 1.0f);
}

__global__ void k_fill(const int* __restrict__ ei32) {
    int e = blockIdx.x * blockDim.x + threadIdx.x;
    if (e >= NE) return;
    int s, d;
    load_edge(ei32, e, s, d);
    int pos = atomicAdd(&g_fill[d], 1);
    g_srcs[pos] = s;
}

// warp per dst: lanes 0..23 own channels; edges streamed through L2
__global__ void k_gather(const float* __restrict__ x) {
    int w = (blockIdx.x * blockDim.x + threadIdx.x) >> 5;
    int lane = threadIdx.x & 31;
    if (w >= NN || lane >= 24) return;
    int start = g_off[w];
    int end = (w + 1 < NN) ? g_off[w + 1] : NE;
    float acc = 0.0f;
    for (int e = start; e < end; e++) {
        int s = g_srcs[e];
        acc = fmaf(g_dinv[s], __ldg(x + (size_t)s * 24 + lane), acc);
    }
    g_agg[(size_t)w * 24 + lane] = acc;
}

// ---------------- fast math (MUFU-based) ----------------
__device__ __forceinline__ float fsigmoid(float x) {
    float e, r;
    asm("ex2.approx.ftz.f32 %0, %1;" : "=f"(e) : "f"(-x * 1.4426950408889634f));
    asm("rcp.approx.ftz.f32 %0, %1;" : "=f"(r) : "f"(1.0f + e));
    return r;
}
__device__ __forceinline__ float ftanh(float x) {
    float r;
    asm("tanh.approx.f32 %0, %1;" : "=f"(r) : "f"(x));
    return r;
}

// ---------------- bf16 helpers ----------------
__device__ __forceinline__ float fhi(float x) {
    return __bfloat162float(__float2bfloat16_rn(x));
}
__device__ __forceinline__ uint32_t pk(float a, float b) {
    __nv_bfloat162 t = __floats2bfloat162_rn(a, b);
    return *reinterpret_cast<uint32_t*>(&t);
}
__device__ __forceinline__ float2 upk(uint32_t u) {
    __nv_bfloat162 t = *reinterpret_cast<__nv_bfloat162*>(&u);
    return make_float2(__low2float(t), __high2float(t));
}

// m16n8k16 row.col bf16 MMA, fp32 accumulate
__device__ __forceinline__ void mma16816(float* d, const uint32_t* a,
                                         uint32_t b0, uint32_t b1) {
    asm volatile(
        "mma.sync.aligned.m16n8k16.row.col.f32.bf16.bf16.f32 "
        "{%0,%1,%2,%3}, {%4,%5,%6,%7}, {%8,%9}, {%0,%1,%2,%3};"
        : "+f"(d[0]), "+f"(d[1]), "+f"(d[2]), "+f"(d[3])
        : "r"(a[0]), "r"(a[1]), "r"(a[2]), "r"(a[3]), "r"(b0), "r"(b1));
}

// ---------------- smem layout (bytes) ----------------
#define SM_B1    0          // 128 frags x 32 lanes x 16B = 64KB (rz: K=128,N=128)
#define SM_B2    65536      // 16KB (Wih_n: K=64,N=64)
#define SM_B3    81920      // 16KB (Whh_n)
#define SM_XA    98304      // float2[12][128] = 12KB
#define SM_WG3   110592     // float4[64] : {wg0, wg1, bg, 0}
#define SM_BIAS  111616     // float4[64] : {br, bz, bin, bhn}
#define SM_WFC   112640     // float[64]
#define SM_TOTAL 112896     // 2 CTAs per SM

__global__ void __launch_bounds__(256, 2)
k_fused(const float* __restrict__ x,
        const float* __restrict__ W_gcn, const float* __restrict__ b_gcn,
        const float* __restrict__ W_ih,  const float* __restrict__ W_hh,
        const float* __restrict__ b_ih,  const float* __restrict__ b_hh,
        const float* __restrict__ W_fc,  const float* __restrict__ b_fc,
        float* __restrict__ out) {
    extern __shared__ char smem[];
    const int tid  = threadIdx.x;
    const int wid  = tid >> 5;
    const int lane = tid & 31;
    const int gid  = lane >> 2;
    const int tig  = lane & 3;
    const int node0 = blockIdx.x * NPB;
    const int n0 = wid * 16 + gid;
    const int n1 = n0 + 8;

    // ---- build B fragments (hi/lo interleaved, fragment-major) ----
    for (int i = tid; i < 6144; i += 256) {
        int f, l;
        const float* Wrow;
        int k0;
        uint32_t dst;
        if (i < 4096) {                       // B1: rz, 8kt x 16nt
            f = i >> 5; l = i & 31;
            int kt = f >> 4, nt = f & 15;
            int g = l >> 2, tg = l & 3;
            int j = 8 * nt + g;
            k0 = 16 * kt + 2 * tg;
            Wrow = (kt < 4) ? (W_ih + j * 64 + k0) : (W_hh + j * 64 + (k0 - 64));
            dst = SM_B1 + (uint32_t)(f * 32 + l) * 16;
        } else if (i < 5120) {                // B2: Wih_n
            int ii = i - 4096;
            f = ii >> 5; l = ii & 31;
            int kt = f >> 3, nt = f & 7;
            int g = l >> 2, tg = l & 3;
            int j = 8 * nt + g;
            k0 = 16 * kt + 2 * tg;
            Wrow = W_ih + (128 + j) * 64 + k0;
            dst = SM_B2 + (uint32_t)(f * 32 + l) * 16;
        } else {                              // B3: Whh_n
            int ii = i - 5120;
            f = ii >> 5; l = ii & 31;
            int kt = f >> 3, nt = f & 7;
            int g = l >> 2, tg = l & 3;
            int j = 8 * nt + g;
            k0 = 16 * kt + 2 * tg;
            Wrow = W_hh + (128 + j) * 64 + k0;
            dst = SM_B3 + (uint32_t)(f * 32 + l) * 16;
        }
        float w0 = Wrow[0], w1 = Wrow[1], w8 = Wrow[8], w9 = Wrow[9];
        float h0 = fhi(w0), h1 = fhi(w1), h8 = fhi(w8), h9 = fhi(w9);
        uint4 v;
        v.x = pk(h0, h1);
        v.y = pk(h8, h9);
        v.z = pk(w0 - h0, w1 - h1);
        v.w = pk(w8 - h8, w9 - h9);
        *(uint4*)(smem + dst) = v;
    }

    // ---- XA: dinv*(agg_raw + dinv*x), layout float2[t][n] ----
    float* sXA = (float*)(smem + SM_XA);
    for (int i = tid; i < NPB * 24; i += 256) {
        int n = i / 24, cc = i - n * 24;
        int t = cc >> 1, c = cc & 1;
        int node = node0 + n;
        float v = 0.0f;
        if (node < NN) {
            float dv = g_dinv[node];
            v = dv * (g_agg[(size_t)node * 24 + cc] + dv * x[(size_t)node * 24 + cc]);
        }
        sXA[(t * 128 + n) * 2 + c] = v;
    }
    if (tid < 64) {
        float4* wg3 = (float4*)(smem + SM_WG3);
        wg3[tid] = make_float4(W_gcn[tid], W_gcn[64 + tid], b_gcn[tid], 0.0f);
        float4* bia = (float4*)(smem + SM_BIAS);
        bia[tid] = make_float4(b_ih[tid] + b_hh[tid],
                               b_ih[64 + tid] + b_hh[64 + tid],
                               b_ih[128 + tid], b_hh[128 + tid]);
        ((float*)(smem + SM_WFC))[tid] = W_fc[tid];
    }
    __syncthreads();

    const float4* sWG3  = (const float4*)(smem + SM_WG3);
    const float4* sBIAS = (const float4*)(smem + SM_BIAS);
    const float*  sWFC  = (const float*)(smem + SM_WFC);

    // ---- hidden state kept PACKED as bf16 hi/lo A-fragments ----
    uint32_t hh[4][4], hl[4][4];
#pragma unroll
    for (int kt = 0; kt < 4; kt++)
#pragma unroll
        for (int q = 0; q < 4; q++) { hh[kt][q] = 0u; hl[kt][q] = 0u; }

#pragma unroll 1
    for (int t = 0; t < TT; t++) {
        float2 xaA = *(const float2*)(sXA + (t * 128 + n0) * 2);
        float2 xaB = *(const float2*)(sXA + (t * 128 + n1) * 2);

        // ---- S fragments (hi/lo) ----
        uint32_t sfH[4][4], sfL[4][4];
#pragma unroll
        for (int kt = 0; kt < 4; kt++) {
            int k0 = 16 * kt + 2 * tig;
            float4 g0 = sWG3[k0], g1 = sWG3[k0 + 1];
            float4 g8 = sWG3[k0 + 8], g9 = sWG3[k0 + 9];
            float s00 = fmaxf(fmaf(xaA.x, g0.x, fmaf(xaA.y, g0.y, g0.z)), 0.0f);
            float s01 = fmaxf(fmaf(xaA.x, g1.x, fmaf(xaA.y, g1.y, g1.z)), 0.0f);
            float s10 = fmaxf(fmaf(xaB.x, g0.x, fmaf(xaB.y, g0.y, g0.z)), 0.0f);
            float s11 = fmaxf(fmaf(xaB.x, g1.x, fmaf(xaB.y, g1.y, g1.z)), 0.0f);
            float s08 = fmaxf(fmaf(xaA.x, g8.x, fmaf(xaA.y, g8.y, g8.z)), 0.0f);
            float s09 = fmaxf(fmaf(xaA.x, g9.x, fmaf(xaA.y, g9.y, g9.z)), 0.0f);
            float s18 = fmaxf(fmaf(xaB.x, g8.x, fmaf(xaB.y, g8.y, g8.z)), 0.0f);
            float s19 = fmaxf(fmaf(xaB.x, g9.x, fmaf(xaB.y, g9.y, g9.z)), 0.0f);
            float h00 = fhi(s00), h01 = fhi(s01), h10 = fhi(s10), h11 = fhi(s11);
            float h08 = fhi(s08), h09 = fhi(s09), h18 = fhi(s18), h19 = fhi(s19);
            sfH[kt][0] = pk(h00, h01); sfH[kt][1] = pk(h10, h11);
            sfH[kt][2] = pk(h08, h09); sfH[kt][3] = pk(h18, h19);
            sfL[kt][0] = pk(s00 - h00, s01 - h01);
            sfL[kt][1] = pk(s10 - h10, s11 - h11);
            sfL[kt][2] = pk(s08 - h08, s09 - h09);
            sfL[kt][3] = pk(s18 - h18, s19 - h19);
        }

        // ---- per-nt: accumulate gate tiles, update h, repack ----
        uint32_t nhh[4][4], nhl[4][4];
#pragma unroll
        for (int nt = 0; nt < 8; nt++) {
            float aR[4] = {0, 0, 0, 0}, aZ[4] = {0, 0, 0, 0};
            float aI[4] = {0, 0, 0, 0}, aN[4] = {0, 0, 0, 0};
#pragma unroll
            for (int kt = 0; kt < 8; kt++) {
                const uint32_t* xH = (kt < 4) ? sfH[kt] : hh[kt - 4];
                const uint32_t* xL = (kt < 4) ? sfL[kt] : hl[kt - 4];
                uint4 bR = *(const uint4*)(smem + SM_B1 +
                             (uint32_t)((kt * 16 + nt) * 32 + lane) * 16);
                mma16816(aR, xH, bR.x, bR.y);
                mma16816(aR, xH, bR.z, bR.w);
                mma16816(aR, xL, bR.x, bR.y);
                uint4 bZ = *(const uint4*)(smem + SM_B1 +
                             (uint32_t)((kt * 16 + nt + 8) * 32 + lane) * 16);
                mma16816(aZ, xH, bZ.x, bZ.y);
                mma16816(aZ, xH, bZ.z, bZ.w);
                mma16816(aZ, xL, bZ.x, bZ.y);
                if (kt < 4) {
                    uint4 b2 = *(const uint4*)(smem + SM_B2 +
                                 (uint32_t)((kt * 8 + nt) * 32 + lane) * 16);
                    mma16816(aI, sfH[kt], b2.x, b2.y);
                    mma16816(aI, sfH[kt], b2.z, b2.w);
                    mma16816(aI, sfL[kt], b2.x, b2.y);
                    uint4 b3 = *(const uint4*)(smem + SM_B3 +
                                 (uint32_t)((kt * 8 + nt) * 32 + lane) * 16);
                    mma16816(aN, hh[kt], b3.x, b3.y);
                    mma16816(aN, hh[kt], b3.z, b3.w);
                    mma16816(aN, hl[kt], b3.x, b3.y);
                }
            }
            int kt2 = nt >> 1, base = (nt & 1) * 2;
            float2 oh0H = upk(hh[kt2][base]),     oh0L = upk(hl[kt2][base]);
            float2 oh1H = upk(hh[kt2][base + 1]), oh1L = upk(hl[kt2][base + 1]);
            float hold[4] = { oh0H.x + oh0L.x, oh0H.y + oh0L.y,
                              oh1H.x + oh1L.x, oh1H.y + oh1L.y };
            int j0 = 8 * nt + 2 * tig;
            float4 bj0 = sBIAS[j0];
            float4 bj1 = sBIAS[j0 + 1];
            float hn[4];
#pragma unroll
            for (int q = 0; q < 4; q++) {
                float4 bb = (q & 1) ? bj1 : bj0;
                float r  = fsigmoid(aR[q] + bb.x);
                float z  = fsigmoid(aZ[q] + bb.y);
                float nn = ftanh(fmaf(r, aN[q] + bb.w, aI[q] + bb.z));
                hn[q] = fmaf(z, hold[q] - nn, nn);
            }
            float p0 = fhi(hn[0]), p1 = fhi(hn[1]);
            float p2 = fhi(hn[2]), p3 = fhi(hn[3]);
            nhh[kt2][base]     = pk(p0, p1);
            nhh[kt2][base + 1] = pk(p2, p3);
            nhl[kt2][base]     = pk(hn[0] - p0, hn[1] - p1);
            nhl[kt2][base + 1] = pk(hn[2] - p2, hn[3] - p3);
        }
#pragma unroll
        for (int kt = 0; kt < 4; kt++)
#pragma unroll
            for (int q = 0; q < 4; q++) { hh[kt][q] = nhh[kt][q]; hl[kt][q] = nhl[kt][q]; }
    }

    // ---- FC readout ----
    float pA = 0.0f, pB = 0.0f;
#pragma unroll
    for (int nt = 0; nt < 8; nt++) {
        int kt2 = nt >> 1, base = (nt & 1) * 2;
        float2 aHv = upk(hh[kt2][base]),     aLv = upk(hl[kt2][base]);
        float2 bHv = upk(hh[kt2][base + 1]), bLv = upk(hl[kt2][base + 1]);
        int j0 = 8 * nt + 2 * tig;
        float w0 = sWFC[j0], w1 = sWFC[j0 + 1];
        pA = fmaf(aHv.x + aLv.x, w0, fmaf(aHv.y + aLv.y, w1, pA));
        pB = fmaf(bHv.x + bLv.x, w0, fmaf(bHv.y + bLv.y, w1, pB));
    }
    pA += __shfl_xor_sync(0xFFFFFFFF, pA, 1);
    pA += __shfl_xor_sync(0xFFFFFFFF, pA, 2);
    pB += __shfl_xor_sync(0xFFFFFFFF, pB, 1);
    pB += __shfl_xor_sync(0xFFFFFFFF, pB, 2);
    if (tig == 0) {
        float bfc = b_fc[0];
        int nodeA = node0 + n0;
        int nodeB = node0 + n1;
        if (nodeA < NN) out[nodeA] = pA + bfc;
        if (nodeB < NN) out[nodeB] = pB + bfc;
    }
}

// ---------------- launch ----------------
extern "C" void kernel_launch(void* const* d_in, const int* in_sizes, int n_in,
                              void* d_out, int out_size) {
    const float* x     = (const float*)d_in[0];
    const int*   ei32  = (const int*)d_in[1];   // int32 OR int64 (device-probed)
    const float* W_gcn = (const float*)d_in[2];
    const float* b_gcn = (const float*)d_in[3];
    const float* W_ih  = (const float*)d_in[4];
    const float* W_hh  = (const float*)d_in[5];
    const float* b_ih  = (const float*)d_in[6];
    const float* b_hh  = (const float*)d_in[7];
    const float* W_fc  = (const float*)d_in[8];
    const float* b_fc  = (const float*)d_in[9];
    float* out = (float*)d_out;

    static bool attr_set = false;
    if (!attr_set) {
        cudaFuncSetAttribute(k_fused, cudaFuncAttributeMaxDynamicSharedMemorySize,
                             SM_TOTAL);
        attr_set = true;
    }

    k_initprobe<<<SCAN_BLOCKS, 256>>>(ei32);
    k_count<<<(NE + 255) / 256, 256>>>(ei32);
    k_scan1<<<SCAN_BLOCKS, 256>>>();
    k_scan2<<<1, 256>>>();
    k_scan3<<<SCAN_BLOCKS, 256>>>();
    k_fill<<<(NE + 255) / 256, 256>>>(ei32);
    k_gather<<<(NN * 32 + 255) / 256, 256>>>(x);
    k_fused<<<(NN + NPB - 1) / NPB, 256, SM_TOTAL>>>(
        x, W_gcn, b_gcn, W_ih, W_hh, b_ih, b_hh, W_fc, b_fc, out);
}